// round 3
// baseline (speedup 1.0000x reference)
#include <cuda_runtime.h>
#include <cuda_fp16.h>
#include <cstdint>
#include <cstddef>

// ============================================================================
// RandomGraphMixer3D  ==  D[M=BT*N, 32] = gather(A)[M,512] @ W'[512,32] + bias
//   A[(b,n), r*32+c] = x[b,c,idx[n,r]]  (fp16-gathered, 64B-contiguous after xt)
// sm_100-safe path: cp.async gather ring + ldmatrix + mma.sync m16n8k16 f16,
// f32 accumulation. No tcgen05 (target lacks the 'a' feature suffix).
// ============================================================================

#define BT_     16
#define NNODES_ 32768
#define NR_     16
#define NTILES_ 4096          // BT_ * NNODES_/128
#define NBUF_   6
#define PF_     3

// SMEM layout (bytes)
#define OFF_B    0            // 32 o-rows x 1040B (512 halves + 16B pad)
#define OFF_IDX  33280        // 2 x 8192 (128 rows x 16 ints)
#define OFF_BIAS 49664        // 128 B
#define OFF_A    49920        // 6 bufs x (128 rows x 80B)
#define ABUF_SZ  10240
#define SMEM_TOTAL (49920 + NBUF_*ABUF_SZ)   // 111360

__device__ __forceinline__ uint32_t smem_u32(const void* p) {
    uint32_t a;
    asm("{ .reg .u64 t; cvta.to.shared.u64 t, %1; cvt.u32.u64 %0, t; }" : "=r"(a) : "l"(p));
    return a;
}
__device__ __forceinline__ void cp_async16(uint32_t dst, const void* src) {
    asm volatile("cp.async.cg.shared.global [%0], [%1], 16;" :: "r"(dst), "l"(src) : "memory");
}
__device__ __forceinline__ void cp_commit() {
    asm volatile("cp.async.commit_group;" ::: "memory");
}
template <int N> __device__ __forceinline__ void cp_wait() {
    asm volatile("cp.async.wait_group %0;" :: "n"(N) : "memory");
}
__device__ __forceinline__ void ldmatrix_x4(uint32_t& r0, uint32_t& r1,
                                            uint32_t& r2, uint32_t& r3, uint32_t a) {
    asm volatile("ldmatrix.sync.aligned.m8n8.x4.shared.b16 {%0,%1,%2,%3}, [%4];"
                 : "=r"(r0), "=r"(r1), "=r"(r2), "=r"(r3) : "r"(a));
}
__device__ __forceinline__ void mma16816(float* c, const uint32_t* a,
                                         uint32_t b0, uint32_t b1) {
    asm volatile(
        "mma.sync.aligned.m16n8k16.row.col.f32.f16.f16.f32 "
        "{%0,%1,%2,%3}, {%4,%5,%6,%7}, {%8,%9}, {%0,%1,%2,%3};"
        : "+f"(c[0]), "+f"(c[1]), "+f"(c[2]), "+f"(c[3])
        : "r"(a[0]), "r"(a[1]), "r"(a[2]), "r"(a[3]), "r"(b0), "r"(b1));
}

// -------- scratch: fp16 transposed x (32 MB) --------------------------------
__device__ __align__(128) __half g_xt[(size_t)BT_ * NNODES_ * 32];

// ============================================================================
// Kernel 1: x[b][c][n] f32 -> xt[b][n][c] f16
// ============================================================================
__global__ void k_transpose(const float* __restrict__ x) {
    __shared__ float tile[32][33];
    int b = blockIdx.x >> 10;
    int n0 = (blockIdx.x & 1023) << 5;
    int tn = threadIdx.x & 31, tc = threadIdx.x >> 5;
    const float* xb = x + ((size_t)b << 20);
#pragma unroll
    for (int p = 0; p < 4; p++) {
        int c = tc + p * 8;
        tile[c][tn] = xb[((size_t)c << 15) + n0 + tn];
    }
    __syncthreads();
    __half* xtb = g_xt + ((size_t)b << 20);
    int oc = threadIdx.x & 31, on = threadIdx.x >> 5;
#pragma unroll
    for (int p = 0; p < 4; p++) {
        int n = on + p * 8;
        xtb[(size_t)(n0 + n) * 32 + oc] = __float2half(tile[oc][n]);
    }
}

// ============================================================================
// Kernel 2: persistent gather-GEMM (148 CTAs x 256 threads)
// ============================================================================
__global__ void __launch_bounds__(256, 1)
k_main(const float* __restrict__ w, const float* __restrict__ bias,
       const int* __restrict__ idxg, float* __restrict__ out) {
    extern __shared__ char smem[];
    uint32_t sb = smem_u32(smem);
    int tid = threadIdx.x;
    int wid = tid >> 5, lane = tid & 31;

    // ---- B image: B_s[o][k] halves, row stride 1040B (pad kills conflicts) --
    {
        __half* Bs = (__half*)(smem + OFF_B);
        for (int e = tid; e < 32 * 512; e += 256) {
            int o = e >> 9, k = e & 511;
            Bs[o * 520 + k] = __float2half(w[o * 512 + (k & 31) * 16 + (k >> 5)]);
        }
        if (tid < 32) ((float*)(smem + OFF_BIAS))[tid] = bias[tid];
    }

    // tiles for this CTA: t_i = blockIdx.x + i*gridDim.x
    int nt = 0;
    for (int t = blockIdx.x; t < NTILES_; t += gridDim.x) nt++;
    if (nt == 0) { __syncthreads(); return; }

    const int* idx_s = (const int*)(smem + OFF_IDX);
    const float* bias_s = (const float*)(smem + OFF_BIAS);

    int u  = tid & 3;          // 16B unit within 64B node row
    int rw = tid >> 2;         // 0..63 base row

    // gather one r-stage of tile t into buffer buf
    auto gather = [&](int t, int r, int buf) {
        int b  = t >> 8;
        int ib = (t / 148) & 1;                     // idx slot for this tile
        const char* xtb = (const char*)(g_xt + ((size_t)b << 20));
        uint32_t abase = sb + OFF_A + (uint32_t)buf * ABUF_SZ;
        const int* id = idx_s + ib * 2048;
#pragma unroll
        for (int p = 0; p < 2; p++) {
            int row = rw + p * 64;
            int g = id[row * NR_ + r];
            cp_async16(abase + (uint32_t)row * 80 + (uint32_t)u * 16,
                       xtb + (size_t)g * 64 + u * 16);
        }
    };
    auto idx_load = [&](int t) {                    // 8 KB -> slot (t/148)&1
        int ib = (t / 148) & 1;
        int nb = (t & 255) << 7;
        const int4* src = (const int4*)(idxg + (size_t)nb * NR_);
        uint32_t dst = sb + OFF_IDX + (uint32_t)ib * 8192;
#pragma unroll
        for (int k = 0; k < 2; k++)
            cp_async16(dst + (uint32_t)(tid + k * 256) * 16, src + tid + k * 256);
    };

    // ---- prologue: idx tile0, then prefetch stages 0..PF-1 ----
    int t0 = blockIdx.x;
    idx_load(t0);
    cp_commit();
    cp_wait<0>();
    __syncthreads();
#pragma unroll
    for (int s = 0; s < PF_; s++) { gather(t0, s, s); cp_commit(); }

    // warp tiling: n-block = wid>>1 (8 o's), m-half = wid&1 (64 rows)
    int mh = wid & 1, nb_o = wid >> 1;
    uint32_t a_warp = sb + OFF_A;                   // + buf*ABUF_SZ later
    uint32_t a_lane = (uint32_t)(mh * 64 + (lane & 15)) * 80 + ((lane >> 4) << 4);
    uint32_t b_lane = sb + OFF_B + (uint32_t)((nb_o * 8 + (lane >> 2)) * 1040
                                              + 2 * (lane & 3) * 2);

    int cons_buf = 0, pf_buf = PF_;
    int pf_i = 0, pf_r = PF_;                       // prefetch cursor (tile idx i, r)

    for (int i = 0; i < nt; i++) {
        int t = blockIdx.x + i * 148;
        int b = t >> 8;
        int nb_node = (t & 255) << 7;

        float C[4][4];
#pragma unroll
        for (int m = 0; m < 4; m++)
#pragma unroll
            for (int j = 0; j < 4; j++) C[m][j] = 0.0f;

        for (int r = 0; r < NR_; r++) {
            // issue prefetch stage (pf_i, pf_r)
            if (pf_i < nt) gather(blockIdx.x + pf_i * 148, pf_r, pf_buf);
            if (r == 0 && i + 1 < nt) idx_load(blockIdx.x + (i + 1) * 148);
            cp_commit();
            if (++pf_r == NR_) { pf_r = 0; pf_i++; }
            if (++pf_buf == NBUF_) pf_buf = 0;

            cp_wait<PF_>();
            __syncthreads();

            // consume buffer cons_buf: 2 k16-chunks x 4 m-blocks
            uint32_t abuf = a_warp + (uint32_t)cons_buf * ABUF_SZ + a_lane;
            uint32_t bk = b_lane + (uint32_t)r * 64;   // r*32 halves
#pragma unroll
            for (int kc = 0; kc < 2; kc++) {
                uint32_t b0, b1;
                asm volatile("ld.shared.b32 %0, [%1];" : "=r"(b0)
                             : "r"(bk + kc * 32));
                asm volatile("ld.shared.b32 %0, [%1];" : "=r"(b1)
                             : "r"(bk + kc * 32 + 16));
#pragma unroll
                for (int m = 0; m < 4; m++) {
                    uint32_t a[4];
                    ldmatrix_x4(a[0], a[1], a[2], a[3],
                                abuf + (uint32_t)m * 16 * 80 + kc * 32);
                    mma16816(C[m], a, b0, b1);
                }
            }
            if (++cons_buf == NBUF_) cons_buf = 0;
        }

        // ---- epilogue: bias + store (C frag: rows=nodes, cols=o) ----
        {
            int o = nb_o * 8 + 2 * (lane & 3);
            float bo0 = bias_s[o], bo1 = bias_s[o + 1];
            float* ob = out + ((size_t)b << 20) + ((size_t)o << 15)
                      + nb_node + mh * 64 + (lane >> 2);
#pragma unroll
            for (int m = 0; m < 4; m++) {
                float* p = ob + m * 16;
                p[0]             = C[m][0] + bo0;
                p[1 << 15]       = C[m][1] + bo1;
                p[8]             = C[m][2] + bo0;
                p[(1 << 15) + 8] = C[m][3] + bo1;
            }
        }
    }
}

// ============================================================================
extern "C" void kernel_launch(void* const* d_in, const int* in_sizes, int n_in,
                              void* d_out, int out_size) {
    const float* x    = (const float*)d_in[0];
    const float* w    = (const float*)d_in[1];
    const float* bias = (const float*)d_in[2];
    const int*   idx  = (const int*)d_in[3];
    float* out = (float*)d_out;

    (void)cudaFuncSetAttribute(k_main, cudaFuncAttributeMaxDynamicSharedMemorySize,
                               SMEM_TOTAL);

    k_transpose<<<BT_ * (NNODES_ / 32), 256>>>(x);
    k_main<<<148, 256, SMEM_TOTAL>>>(w, bias, idx, out);
}

// round 4
// speedup vs baseline: 1.1082x; 1.1082x over previous
#include <cuda_runtime.h>
#include <cuda_fp16.h>
#include <cstdint>
#include <cstddef>

// ============================================================================
// RandomGraphMixer3D  ==  D[M=BT*N, 32] = gather(A)[M,512] @ W'[512,32] + bias
//   A[(b,n), r*32+c] = x[b,c,idx[n,r]]  (fp16-gathered, 64B-contiguous after xt)
// sm_100-safe path: cp.async gather ring + ldmatrix + mma.sync m16n8k16 f16,
// f32 accumulation. 2 CTAs/SM for latency hiding (L1-wavefront bound).
// ============================================================================

#define BT_     16
#define NNODES_ 32768
#define NR_     16
#define NTILES_ 4096          // BT_ * NNODES_/128
#define NBUF_   5
#define PF_     3             // must satisfy PF_+1 < NBUF_ (ring write-race)
#define GRID_   296           // 2 CTAs per SM

// SMEM layout (bytes)
#define OFF_B    0            // 32 o-rows x 1040B (512 halves + 16B pad)
#define OFF_IDX  33280        // 2 slots x 10240 (128 rows x 80B: 16 ints + 16B pad)
#define OFF_BIAS 53760        // 128 B
#define OFF_A    53888        // 5 bufs x (128 rows x 80B)
#define ABUF_SZ  10240
#define SMEM_TOTAL (53888 + NBUF_*ABUF_SZ)   // 105088 -> 2 CTAs/SM fits 228KB

__device__ __forceinline__ uint32_t smem_u32(const void* p) {
    uint32_t a;
    asm("{ .reg .u64 t; cvta.to.shared.u64 t, %1; cvt.u32.u64 %0, t; }" : "=r"(a) : "l"(p));
    return a;
}
__device__ __forceinline__ void cp_async16(uint32_t dst, const void* src) {
    asm volatile("cp.async.cg.shared.global [%0], [%1], 16;" :: "r"(dst), "l"(src) : "memory");
}
__device__ __forceinline__ void cp_commit() {
    asm volatile("cp.async.commit_group;" ::: "memory");
}
template <int N> __device__ __forceinline__ void cp_wait() {
    asm volatile("cp.async.wait_group %0;" :: "n"(N) : "memory");
}
__device__ __forceinline__ void ldmatrix_x4(uint32_t& r0, uint32_t& r1,
                                            uint32_t& r2, uint32_t& r3, uint32_t a) {
    asm volatile("ldmatrix.sync.aligned.m8n8.x4.shared.b16 {%0,%1,%2,%3}, [%4];"
                 : "=r"(r0), "=r"(r1), "=r"(r2), "=r"(r3) : "r"(a));
}
__device__ __forceinline__ void mma16816(float* c, const uint32_t* a,
                                         uint32_t b0, uint32_t b1) {
    asm volatile(
        "mma.sync.aligned.m16n8k16.row.col.f32.f16.f16.f32 "
        "{%0,%1,%2,%3}, {%4,%5,%6,%7}, {%8,%9}, {%0,%1,%2,%3};"
        : "+f"(c[0]), "+f"(c[1]), "+f"(c[2]), "+f"(c[3])
        : "r"(a[0]), "r"(a[1]), "r"(a[2]), "r"(a[3]), "r"(b0), "r"(b1));
}

// -------- scratch: fp16 transposed x (32 MB) --------------------------------
__device__ __align__(128) __half g_xt[(size_t)BT_ * NNODES_ * 32];

// ============================================================================
// Kernel 1: x[b][c][n] f32 -> xt[b][n][c] f16
// ============================================================================
__global__ void k_transpose(const float* __restrict__ x) {
    __shared__ float tile[32][33];
    int b = blockIdx.x >> 10;
    int n0 = (blockIdx.x & 1023) << 5;
    int tn = threadIdx.x & 31, tc = threadIdx.x >> 5;
    const float* xb = x + ((size_t)b << 20);
#pragma unroll
    for (int p = 0; p < 4; p++) {
        int c = tc + p * 8;
        tile[c][tn] = xb[((size_t)c << 15) + n0 + tn];
    }
    __syncthreads();
    __half* xtb = g_xt + ((size_t)b << 20);
    int oc = threadIdx.x & 31, on = threadIdx.x >> 5;
#pragma unroll
    for (int p = 0; p < 4; p++) {
        int n = on + p * 8;
        xtb[(size_t)(n0 + n) * 32 + oc] = __float2half(tile[oc][n]);
    }
}

// ============================================================================
// Kernel 2: persistent gather-GEMM (296 CTAs x 256 threads, 2/SM)
// ============================================================================
__global__ void __launch_bounds__(256, 2)
k_main(const float* __restrict__ w, const float* __restrict__ bias,
       const int* __restrict__ idxg, float* __restrict__ out) {
    extern __shared__ char smem[];
    uint32_t sb = smem_u32(smem);
    int tid = threadIdx.x;
    int wid = tid >> 5, lane = tid & 31;

    // ---- B image: B_s[o][k] halves, row stride 1040B (pad kills conflicts) --
    {
        __half* Bs = (__half*)(smem + OFF_B);
        for (int e = tid; e < 32 * 512; e += 256) {
            int o = e >> 9, k = e & 511;
            Bs[o * 520 + k] = __float2half(w[o * 512 + (k & 31) * 16 + (k >> 5)]);
        }
        if (tid < 32) ((float*)(smem + OFF_BIAS))[tid] = bias[tid];
    }

    int nt = 0;
    for (int t = blockIdx.x; t < NTILES_; t += GRID_) nt++;
    if (nt == 0) { __syncthreads(); return; }

    const int* idx_s = (const int*)(smem + OFF_IDX);
    const float* bias_s = (const float*)(smem + OFF_BIAS);

    int u  = tid & 3;          // 16B unit within 64B node row
    int rw = tid >> 2;         // 0..63 base row

    // gather one r-stage of tile (iter i) into buffer buf; idx slot = i&1
    auto gather = [&](int i, int r, int buf) {
        int t = blockIdx.x + i * GRID_;
        int b = t >> 8;
        const char* xtb = (const char*)(g_xt + ((size_t)b << 20));
        uint32_t abase = sb + OFF_A + (uint32_t)buf * ABUF_SZ;
        const int* id = idx_s + (i & 1) * 2560;    // padded rows: 20 ints
#pragma unroll
        for (int p = 0; p < 2; p++) {
            int row = rw + p * 64;
            int g = id[row * 20 + r];
            cp_async16(abase + (uint32_t)row * 80 + (uint32_t)u * 16,
                       xtb + (size_t)g * 64 + u * 16);
        }
    };
    // idx tile (8 KB useful) -> padded slot (i&1): row stride 80 B
    auto idx_load = [&](int i) {
        int t = blockIdx.x + i * GRID_;
        int nb = (t & 255) << 7;
        const int4* src = (const int4*)(idxg + (size_t)nb * NR_);
        uint32_t dst = sb + OFF_IDX + (uint32_t)(i & 1) * 10240;
#pragma unroll
        for (int k = 0; k < 2; k++) {
            int j = tid + k * 256;                 // int4 index 0..511
            cp_async16(dst + (uint32_t)(j >> 2) * 80 + (uint32_t)(j & 3) * 16,
                       src + j);
        }
    };

    // ---- prologue ----
    idx_load(0);
    cp_commit();
    cp_wait<0>();
    __syncthreads();
#pragma unroll
    for (int s = 0; s < PF_; s++) { gather(0, s, s); cp_commit(); }

    // warp tiling: n-block = wid>>1 (8 o's), m-half = wid&1 (64 rows)
    int mh = wid & 1, nb_o = wid >> 1;
    uint32_t a_warp = sb + OFF_A;
    uint32_t a_lane = (uint32_t)(mh * 64 + (lane & 15)) * 80 + ((lane >> 4) << 4);
    uint32_t b_lane = sb + OFF_B + (uint32_t)((nb_o * 8 + (lane >> 2)) * 1040
                                              + 2 * (lane & 3) * 2);

    int cons_buf = 0, pf_buf = PF_;
    int pf_i = 0, pf_r = PF_;

    for (int i = 0; i < nt; i++) {
        int t = blockIdx.x + i * GRID_;
        int b = t >> 8;
        int nb_node = (t & 255) << 7;

        float C[4][4];
#pragma unroll
        for (int m = 0; m < 4; m++)
#pragma unroll
            for (int j = 0; j < 4; j++) C[m][j] = 0.0f;

        for (int r = 0; r < NR_; r++) {
            if (pf_i < nt) gather(pf_i, pf_r, pf_buf);
            if (r == 0 && i + 1 < nt) idx_load(i + 1);
            cp_commit();
            if (++pf_r == NR_) { pf_r = 0; pf_i++; }
            if (++pf_buf == NBUF_) pf_buf = 0;

            cp_wait<PF_>();
            __syncthreads();

            uint32_t abuf = a_warp + (uint32_t)cons_buf * ABUF_SZ + a_lane;
            uint32_t bk = b_lane + (uint32_t)r * 64;
#pragma unroll
            for (int kc = 0; kc < 2; kc++) {
                uint32_t b0, b1;
                asm volatile("ld.shared.b32 %0, [%1];" : "=r"(b0)
                             : "r"(bk + kc * 32));
                asm volatile("ld.shared.b32 %0, [%1];" : "=r"(b1)
                             : "r"(bk + kc * 32 + 16));
#pragma unroll
                for (int m = 0; m < 4; m++) {
                    uint32_t a[4];
                    ldmatrix_x4(a[0], a[1], a[2], a[3],
                                abuf + (uint32_t)m * 16 * 80 + kc * 32);
                    mma16816(C[m], a, b0, b1);
                }
            }
            if (++cons_buf == NBUF_) cons_buf = 0;
        }

        // ---- epilogue: bias + store (C frag: rows=nodes, cols=o) ----
        {
            int o = nb_o * 8 + 2 * (lane & 3);
            float bo0 = bias_s[o], bo1 = bias_s[o + 1];
            float* ob = out + ((size_t)b << 20) + ((size_t)o << 15)
                      + nb_node + mh * 64 + (lane >> 2);
#pragma unroll
            for (int m = 0; m < 4; m++) {
                float* p = ob + m * 16;
                p[0]             = C[m][0] + bo0;
                p[1 << 15]       = C[m][1] + bo1;
                p[8]             = C[m][2] + bo0;
                p[(1 << 15) + 8] = C[m][3] + bo1;
            }
        }
    }
}

// ============================================================================
extern "C" void kernel_launch(void* const* d_in, const int* in_sizes, int n_in,
                              void* d_out, int out_size) {
    const float* x    = (const float*)d_in[0];
    const float* w    = (const float*)d_in[1];
    const float* bias = (const float*)d_in[2];
    const int*   idx  = (const int*)d_in[3];
    float* out = (float*)d_out;

    (void)cudaFuncSetAttribute(k_main, cudaFuncAttributeMaxDynamicSharedMemorySize,
                               SMEM_TOTAL);

    k_transpose<<<BT_ * (NNODES_ / 32), 256>>>(x);
    k_main<<<GRID_, 256, SMEM_TOTAL>>>(w, bias, idx, out);
}

// round 5
// speedup vs baseline: 1.2646x; 1.1412x over previous
#include <cuda_runtime.h>
#include <cuda_fp16.h>
#include <cstdint>
#include <cstddef>

// ============================================================================
// RandomGraphMixer3D  ==  D[M=BT*N, 32] = gather(A)[M,512] @ W'[512,32] + bias
// fp16 gather ring + ldmatrix + mma.sync m16n8k16, f32 accum.
// R5: warp tiling 8x(m16 x n32) -> A fragments loaded once (ldmatrix wf /4),
//     B served from a precomputed per-lane fragment table (2x lds.v4/warp/kc).
// ============================================================================

#define BT_     16
#define NNODES_ 32768
#define NR_     16
#define NTILES_ 4096
#define NBUF_   5
#define PF_     3             // PF_+1 < NBUF_
#define GRID_   296           // 2 CTAs/SM

// SMEM layout (bytes)
#define OFF_B    0            // 32 KB B-frag table
#define OFF_IDX  32768        // 2 slots x 10240 (128 rows x 80B padded)
#define OFF_BIAS 53248        // 128 B
#define OFF_A    53376        // 5 bufs x (128 rows x 80B)
#define ABUF_SZ  10240
#define SMEM_TOTAL (53376 + NBUF_*ABUF_SZ)   // 104576 -> 2 CTAs/SM

__device__ __forceinline__ uint32_t smem_u32(const void* p) {
    uint32_t a;
    asm("{ .reg .u64 t; cvta.to.shared.u64 t, %1; cvt.u32.u64 %0, t; }" : "=r"(a) : "l"(p));
    return a;
}
__device__ __forceinline__ void cp_async16(uint32_t dst, const void* src) {
    asm volatile("cp.async.cg.shared.global [%0], [%1], 16;" :: "r"(dst), "l"(src) : "memory");
}
__device__ __forceinline__ void cp_commit() {
    asm volatile("cp.async.commit_group;" ::: "memory");
}
template <int N> __device__ __forceinline__ void cp_wait() {
    asm volatile("cp.async.wait_group %0;" :: "n"(N) : "memory");
}
__device__ __forceinline__ void ldmatrix_x4(uint32_t& r0, uint32_t& r1,
                                            uint32_t& r2, uint32_t& r3, uint32_t a) {
    asm volatile("ldmatrix.sync.aligned.m8n8.x4.shared.b16 {%0,%1,%2,%3}, [%4];"
                 : "=r"(r0), "=r"(r1), "=r"(r2), "=r"(r3) : "r"(a));
}
__device__ __forceinline__ void lds128(uint32_t* v, uint32_t a) {
    asm volatile("ld.shared.v4.b32 {%0,%1,%2,%3}, [%4];"
                 : "=r"(v[0]), "=r"(v[1]), "=r"(v[2]), "=r"(v[3]) : "r"(a));
}
__device__ __forceinline__ void mma16816(float* c, const uint32_t* a,
                                         uint32_t b0, uint32_t b1) {
    asm volatile(
        "mma.sync.aligned.m16n8k16.row.col.f32.f16.f16.f32 "
        "{%0,%1,%2,%3}, {%4,%5,%6,%7}, {%8,%9}, {%0,%1,%2,%3};"
        : "+f"(c[0]), "+f"(c[1]), "+f"(c[2]), "+f"(c[3])
        : "r"(a[0]), "r"(a[1]), "r"(a[2]), "r"(a[3]), "r"(b0), "r"(b1));
}

// -------- scratch ------------------------------------------------------------
__device__ __align__(128) __half   g_xt[(size_t)BT_ * NNODES_ * 32];  // 32 MB
__device__ __align__(128) uint32_t g_Bfrag[8192];                      // 32 KB

// ============================================================================
// Kernel 1: x[b][c][n] f32 -> xt[b][n][c] f16
// ============================================================================
__global__ void k_transpose(const float* __restrict__ x) {
    __shared__ float tile[32][33];
    int b = blockIdx.x >> 10;
    int n0 = (blockIdx.x & 1023) << 5;
    int tn = threadIdx.x & 31, tc = threadIdx.x >> 5;
    const float* xb = x + ((size_t)b << 20);
#pragma unroll
    for (int p = 0; p < 4; p++) {
        int c = tc + p * 8;
        tile[c][tn] = xb[((size_t)c << 15) + n0 + tn];
    }
    __syncthreads();
    __half* xtb = g_xt + ((size_t)b << 20);
    int oc = threadIdx.x & 31, on = threadIdx.x >> 5;
#pragma unroll
    for (int p = 0; p < 4; p++) {
        int n = on + p * 8;
        xtb[(size_t)(n0 + n) * 32 + oc] = __float2half(tile[oc][n]);
    }
}

// ============================================================================
// Kernel 1b: build per-lane B fragment table.
// Entry u32 e: lane=(e>>2)&31, j=e&3, chunk=(e>>7)&1, kc=(e>>8)&1, r=e>>9.
// nb = chunk*2 + (j>>1), reg = j&1; n_o = nb*8 + (lane>>2);
// c = kc*16 + 2*(lane&3) + reg*8; value = half2(W'[n_o][r*32+c], [..c+1]).
// Matches mma.m16n8k16 B layout validated in R3/R4.
// ============================================================================
__global__ void k_bfrag(const float* __restrict__ w) {
    for (int e = threadIdx.x; e < 8192; e += blockDim.x) {
        int lane = (e >> 2) & 31, j = e & 3;
        int chunk = (e >> 7) & 1, kc = (e >> 8) & 1, r = e >> 9;
        int nb = chunk * 2 + (j >> 1), reg = j & 1;
        int n_o = nb * 8 + (lane >> 2);
        int c = kc * 16 + 2 * (lane & 3) + reg * 8;
        __half lo = __float2half(w[n_o * 512 + c * 16 + r]);
        __half hi = __float2half(w[n_o * 512 + (c + 1) * 16 + r]);
        __half2 v = __halves2half2(lo, hi);
        g_Bfrag[e] = *(uint32_t*)&v;
    }
}

// ============================================================================
// Kernel 2: persistent gather-GEMM (296 CTAs x 256 threads, 2/SM)
// ============================================================================
__global__ void __launch_bounds__(256, 2)
k_main(const float* __restrict__ bias, const int* __restrict__ idxg,
       float* __restrict__ out) {
    extern __shared__ char smem[];
    uint32_t sb = smem_u32(smem);
    int tid = threadIdx.x;
    int wid = tid >> 5, lane = tid & 31;

    int nt = 0;
    for (int t = blockIdx.x; t < NTILES_; t += GRID_) nt++;

    const int* idx_s = (const int*)(smem + OFF_IDX);
    const float* bias_s = (const float*)(smem + OFF_BIAS);

    int u  = tid & 3;          // 16B unit within 64B node row
    int rw = tid >> 2;         // 0..63 base row

    auto gather = [&](int i, int r, int buf) {
        int t = blockIdx.x + i * GRID_;
        int b = t >> 8;
        const char* xtb = (const char*)(g_xt + ((size_t)b << 20));
        uint32_t abase = sb + OFF_A + (uint32_t)buf * ABUF_SZ;
        const int* id = idx_s + (i & 1) * 2560;
#pragma unroll
        for (int p = 0; p < 2; p++) {
            int row = rw + p * 64;
            int g = id[row * 20 + r];
            cp_async16(abase + (uint32_t)row * 80 + (uint32_t)u * 16,
                       xtb + (size_t)g * 64 + u * 16);
        }
    };
    auto idx_load = [&](int i) {
        int t = blockIdx.x + i * GRID_;
        int nb = (t & 255) << 7;
        const int4* src = (const int4*)(idxg + (size_t)nb * NR_);
        uint32_t dst = sb + OFF_IDX + (uint32_t)(i & 1) * 10240;
#pragma unroll
        for (int k = 0; k < 2; k++) {
            int j = tid + k * 256;
            cp_async16(dst + (uint32_t)(j >> 2) * 80 + (uint32_t)(j & 3) * 16,
                       src + j);
        }
    };

    // ---- prologue: B-frag table + bias + idx tile0, then PF gathers ----
    {
        const char* src = (const char*)g_Bfrag;
        uint32_t dst = sb + OFF_B;
#pragma unroll
        for (int k = 0; k < 8; k++)
            cp_async16(dst + (uint32_t)(tid + k * 256) * 16,
                       src + (tid + k * 256) * 16);
        if (tid < 8)
            cp_async16(sb + OFF_BIAS + (uint32_t)tid * 16,
                       (const char*)bias + tid * 16);
    }
    if (nt == 0) { cp_commit(); cp_wait<0>(); __syncthreads(); return; }
    idx_load(0);
    cp_commit();
    cp_wait<0>();
    __syncthreads();
#pragma unroll
    for (int s = 0; s < PF_; s++) { gather(0, s, s); cp_commit(); }

    // warp tiling: warp owns rows [wid*16, wid*16+16), all 32 outputs
    uint32_t a_warp = sb + OFF_A;
    uint32_t a_lane = (uint32_t)(wid * 16 + (lane & 15)) * 80 + ((lane >> 4) << 4);
    uint32_t b_lane = sb + OFF_B + (uint32_t)lane * 16;   // + (r*2+kc)*1024 + chunk*512

    int cons_buf = 0, pf_buf = PF_;
    int pf_i = 0, pf_r = PF_;

    for (int i = 0; i < nt; i++) {
        int t = blockIdx.x + i * GRID_;
        int b = t >> 8;
        int nb_node = (t & 255) << 7;

        float C[4][4];
#pragma unroll
        for (int m = 0; m < 4; m++)
#pragma unroll
            for (int j = 0; j < 4; j++) C[m][j] = 0.0f;

        for (int r = 0; r < NR_; r++) {
            if (pf_i < nt) gather(pf_i, pf_r, pf_buf);
            if (r == 0 && i + 1 < nt) idx_load(i + 1);
            cp_commit();
            if (++pf_r == NR_) { pf_r = 0; pf_i++; }
            if (++pf_buf == NBUF_) pf_buf = 0;

            cp_wait<PF_>();
            __syncthreads();

            uint32_t abuf = a_warp + (uint32_t)cons_buf * ABUF_SZ + a_lane;
            uint32_t bst = b_lane + (uint32_t)r * 2048;
#pragma unroll
            for (int kc = 0; kc < 2; kc++) {
                uint32_t a[4];
                ldmatrix_x4(a[0], a[1], a[2], a[3], abuf + kc * 32);
                uint32_t bf0[4], bf1[4];
                lds128(bf0, bst + (uint32_t)kc * 1024);         // nb0,nb1
                lds128(bf1, bst + (uint32_t)kc * 1024 + 512);   // nb2,nb3
                mma16816(C[0], a, bf0[0], bf0[1]);
                mma16816(C[1], a, bf0[2], bf0[3]);
                mma16816(C[2], a, bf1[0], bf1[1]);
                mma16816(C[3], a, bf1[2], bf1[3]);
            }
            if (++cons_buf == NBUF_) cons_buf = 0;
        }

        // ---- epilogue: bias + store. C[nb]: rows wid*16+(lane>>2){,+8},
        //      cols o = nb*8 + 2*(lane&3){,+1} ----
        {
            int oo = 2 * (lane & 3);
            float* ob = out + ((size_t)b << 20) + nb_node + wid * 16 + (lane >> 2);
#pragma unroll
            for (int nb = 0; nb < 4; nb++) {
                int o = nb * 8 + oo;
                float bo0 = bias_s[o], bo1 = bias_s[o + 1];
                float* p = ob + ((size_t)o << 15);
                p[0]             = C[nb][0] + bo0;
                p[1 << 15]       = C[nb][1] + bo1;
                p[8]             = C[nb][2] + bo0;
                p[(1 << 15) + 8] = C[nb][3] + bo1;
            }
        }
    }
}

// ============================================================================
extern "C" void kernel_launch(void* const* d_in, const int* in_sizes, int n_in,
                              void* d_out, int out_size) {
    const float* x    = (const float*)d_in[0];
    const float* w    = (const float*)d_in[1];
    const float* bias = (const float*)d_in[2];
    const int*   idx  = (const int*)d_in[3];
    float* out = (float*)d_out;

    (void)cudaFuncSetAttribute(k_main, cudaFuncAttributeMaxDynamicSharedMemorySize,
                               SMEM_TOTAL);

    k_transpose<<<BT_ * (NNODES_ / 32), 256>>>(x);
    k_bfrag<<<1, 256>>>(w);
    k_main<<<GRID_, 256, SMEM_TOTAL>>>(bias, idx, out);
}

// round 6
// speedup vs baseline: 1.4993x; 1.1855x over previous
#include <cuda_runtime.h>
#include <cuda_fp16.h>
#include <cstdint>
#include <cstddef>

// ============================================================================
// RandomGraphMixer3D  ==  D[M=BT*N, 32] = gather(A)[M,512] @ W'[512,32] + bias
// fp16 gather + ldmatrix + mma.sync m16n8k16, f32 accum.
// R6: fully warp-private pipelines -- each warp gathers/consumes its own 16
//     A-rows and idx slice via its own cp.async group ring. ZERO barriers in
//     the main loop. PF=4. Vectorized transpose stores.
// ============================================================================

#define BT_     16
#define NNODES_ 32768
#define NR_     16
#define NTILES_ 4096
#define NBUF_   5
#define PF_     4             // per-warp ring: PF_ < NBUF_
#define GRID_   296           // 2 CTAs/SM

// SMEM layout (bytes)
#define OFF_B    0            // 32 KB B-frag table
#define OFF_BIAS 32768        // 128 B
#define OFF_IDX  32896        // 2 slots x (8 warps x 16 rows x 80B) = 2x10240
#define OFF_A    53376        // 8 warps x 5 bufs x 1280 B
#define WARP_AB  6400         // NBUF_*1280 per warp
#define SMEM_TOTAL (53376 + 8*WARP_AB)   // 104576 -> 2 CTAs/SM

__device__ __forceinline__ uint32_t smem_u32(const void* p) {
    uint32_t a;
    asm("{ .reg .u64 t; cvta.to.shared.u64 t, %1; cvt.u32.u64 %0, t; }" : "=r"(a) : "l"(p));
    return a;
}
__device__ __forceinline__ void cp_async16(uint32_t dst, const void* src) {
    asm volatile("cp.async.cg.shared.global [%0], [%1], 16;" :: "r"(dst), "l"(src) : "memory");
}
__device__ __forceinline__ void cp_commit() {
    asm volatile("cp.async.commit_group;" ::: "memory");
}
template <int N> __device__ __forceinline__ void cp_wait() {
    asm volatile("cp.async.wait_group %0;" :: "n"(N) : "memory");
}
__device__ __forceinline__ void ldmatrix_x4(uint32_t& r0, uint32_t& r1,
                                            uint32_t& r2, uint32_t& r3, uint32_t a) {
    asm volatile("ldmatrix.sync.aligned.m8n8.x4.shared.b16 {%0,%1,%2,%3}, [%4];"
                 : "=r"(r0), "=r"(r1), "=r"(r2), "=r"(r3) : "r"(a));
}
__device__ __forceinline__ void lds128(uint32_t* v, uint32_t a) {
    asm volatile("ld.shared.v4.b32 {%0,%1,%2,%3}, [%4];"
                 : "=r"(v[0]), "=r"(v[1]), "=r"(v[2]), "=r"(v[3]) : "r"(a));
}
__device__ __forceinline__ void mma16816(float* c, const uint32_t* a,
                                         uint32_t b0, uint32_t b1) {
    asm volatile(
        "mma.sync.aligned.m16n8k16.row.col.f32.f16.f16.f32 "
        "{%0,%1,%2,%3}, {%4,%5,%6,%7}, {%8,%9}, {%0,%1,%2,%3};"
        : "+f"(c[0]), "+f"(c[1]), "+f"(c[2]), "+f"(c[3])
        : "r"(a[0]), "r"(a[1]), "r"(a[2]), "r"(a[3]), "r"(b0), "r"(b1));
}

// -------- scratch ------------------------------------------------------------
__device__ __align__(128) __half   g_xt[(size_t)BT_ * NNODES_ * 32];  // 32 MB
__device__ __align__(128) uint32_t g_Bfrag[8192];                      // 32 KB

// ============================================================================
// Kernel 1: x[b][c][n] f32 -> xt[b][n][c] f16 (8-B vectorized stores)
// ============================================================================
__global__ void k_transpose(const float* __restrict__ x) {
    __shared__ float tile[32][33];
    int b = blockIdx.x >> 10;
    int n0 = (blockIdx.x & 1023) << 5;
    int tn = threadIdx.x & 31, tc = threadIdx.x >> 5;
    const float* xb = x + ((size_t)b << 20);
#pragma unroll
    for (int p = 0; p < 4; p++) {
        int c = tc + p * 8;
        tile[c][tn] = xb[((size_t)c << 15) + n0 + tn];
    }
    __syncthreads();
    // write: thread -> node n = tid>>3, quarter q = tid&7 (4 channels, 8 B)
    int n = threadIdx.x >> 3, q = threadIdx.x & 7;
    int c0 = q * 4;
    __half2 h01 = __halves2half2(__float2half(tile[c0][n]),
                                 __float2half(tile[c0 + 1][n]));
    __half2 h23 = __halves2half2(__float2half(tile[c0 + 2][n]),
                                 __float2half(tile[c0 + 3][n]));
    uint2 v = make_uint2(*(uint32_t*)&h01, *(uint32_t*)&h23);
    *(uint2*)((char*)(g_xt + ((size_t)b << 20)) + (size_t)(n0 + n) * 64 + q * 8) = v;
}

// ============================================================================
// Kernel 1b: per-lane B fragment table (layout validated in R5).
// ============================================================================
__global__ void k_bfrag(const float* __restrict__ w) {
    for (int e = threadIdx.x; e < 8192; e += blockDim.x) {
        int lane = (e >> 2) & 31, j = e & 3;
        int chunk = (e >> 7) & 1, kc = (e >> 8) & 1, r = e >> 9;
        int nb = chunk * 2 + (j >> 1), reg = j & 1;
        int n_o = nb * 8 + (lane >> 2);
        int c = kc * 16 + 2 * (lane & 3) + reg * 8;
        __half lo = __float2half(w[n_o * 512 + c * 16 + r]);
        __half hi = __float2half(w[n_o * 512 + (c + 1) * 16 + r]);
        __half2 v = __halves2half2(lo, hi);
        g_Bfrag[e] = *(uint32_t*)&v;
    }
}

// ============================================================================
// Kernel 2: persistent gather-GEMM, warp-autonomous (296 CTAs x 256, 2/SM)
// ============================================================================
__global__ void __launch_bounds__(256, 2)
k_main(const float* __restrict__ bias, const int* __restrict__ idxg,
       float* __restrict__ out) {
    extern __shared__ char smem[];
    uint32_t sb = smem_u32(smem);
    int tid = threadIdx.x;
    int wid = tid >> 5, lane = tid & 31;

    int nt = 0;
    for (int t = blockIdx.x; t < NTILES_; t += GRID_) nt++;

    const float* bias_s = (const float*)(smem + OFF_BIAS);

    // per-warp bases
    uint32_t aw_base  = sb + OFF_A + (uint32_t)wid * WARP_AB;
    uint32_t idx_base = sb + OFF_IDX + (uint32_t)wid * 1280;   // + slot*10240

    int row2 = lane >> 2;              // 0..7 (rows row2, row2+8)
    int u    = lane & 3;               // 16B unit in 64B node row

    // gather one r-stage of iter i into warp-private buffer buf
    auto gather = [&](int i, int r, int buf) {
        int t = blockIdx.x + i * GRID_;
        int b = t >> 8;
        const char* xtb = (const char*)(g_xt + ((size_t)b << 20));
        uint32_t abase = aw_base + (uint32_t)buf * 1280;
        const int* id = (const int*)(smem + (idx_base - sb) + (i & 1) * 10240);
#pragma unroll
        for (int p = 0; p < 2; p++) {
            int row = row2 + p * 8;
            int g = id[row * 20 + r];
            cp_async16(abase + (uint32_t)row * 80 + (uint32_t)u * 16,
                       xtb + (size_t)g * 64 + u * 16);
        }
    };
    // warp-private idx slice: 16 rows x 64 B -> 80 B-padded rows
    auto idx_load = [&](int i) {
        int t = blockIdx.x + i * GRID_;
        int nb = (t & 255) << 7;
        const int4* src = (const int4*)idxg + (size_t)(nb + wid * 16) * 4;
        uint32_t dst = idx_base + (uint32_t)(i & 1) * 10240;
#pragma unroll
        for (int p = 0; p < 2; p++) {
            int e = lane + p * 32;
            int row = e >> 2, q = e & 3;
            cp_async16(dst + (uint32_t)row * 80 + (uint32_t)q * 16,
                       src + row * 4 + q);
        }
    };

    // ---- prologue: B table + bias + idx(0); one barrier; then PF gathers ----
    {
        const char* src = (const char*)g_Bfrag;
#pragma unroll
        for (int k = 0; k < 8; k++)
            cp_async16(sb + OFF_B + (uint32_t)(tid + k * 256) * 16,
                       src + (tid + k * 256) * 16);
        if (tid < 8)
            cp_async16(sb + OFF_BIAS + (uint32_t)tid * 16,
                       (const char*)bias + tid * 16);
        idx_load(0);
        cp_commit();
        cp_wait<0>();
        __syncthreads();     // only barrier in the kernel (B table visibility)
    }
#pragma unroll
    for (int s = 0; s < PF_; s++) { gather(0, s, s); cp_commit(); }

    // consumer addressing (warp owns rows [wid*16, wid*16+16), all 32 o's)
    uint32_t a_lane = aw_base + (uint32_t)(lane & 15) * 80 + ((lane >> 4) << 4);
    uint32_t b_lane = sb + OFF_B + (uint32_t)lane * 16;

    int cons_buf = 0, pf_buf = PF_ % NBUF_;
    int pf_i = 0, pf_r = PF_;

    for (int i = 0; i < nt; i++) {
        int t = blockIdx.x + i * GRID_;
        int b = t >> 8;
        int nb_node = (t & 255) << 7;

        float C[4][4];
#pragma unroll
        for (int m = 0; m < 4; m++)
#pragma unroll
            for (int j = 0; j < 4; j++) C[m][j] = 0.0f;

        for (int r = 0; r < NR_; r++) {
            if (pf_i < nt) gather(pf_i, pf_r, pf_buf);
            if (r == 0 && i + 1 < nt) idx_load(i + 1);
            cp_commit();
            if (++pf_r == NR_) { pf_r = 0; pf_i++; }
            if (++pf_buf == NBUF_) pf_buf = 0;

            cp_wait<PF_>();

            uint32_t abuf = a_lane + (uint32_t)cons_buf * 1280;
            uint32_t bst = b_lane + (uint32_t)r * 2048;
#pragma unroll
            for (int kc = 0; kc < 2; kc++) {
                uint32_t a[4];
                ldmatrix_x4(a[0], a[1], a[2], a[3], abuf + kc * 32);
                uint32_t bf0[4], bf1[4];
                lds128(bf0, bst + (uint32_t)kc * 1024);         // nb0,nb1
                lds128(bf1, bst + (uint32_t)kc * 1024 + 512);   // nb2,nb3
                mma16816(C[0], a, bf0[0], bf0[1]);
                mma16816(C[1], a, bf0[2], bf0[3]);
                mma16816(C[2], a, bf1[0], bf1[1]);
                mma16816(C[3], a, bf1[2], bf1[3]);
            }
            if (++cons_buf == NBUF_) cons_buf = 0;
        }

        // ---- epilogue: bias + store ----
        {
            int oo = 2 * (lane & 3);
            float* ob = out + ((size_t)b << 20) + nb_node + wid * 16 + (lane >> 2);
#pragma unroll
            for (int nb = 0; nb < 4; nb++) {
                int o = nb * 8 + oo;
                float bo0 = bias_s[o], bo1 = bias_s[o + 1];
                float* p = ob + ((size_t)o << 15);
                p[0]             = C[nb][0] + bo0;
                p[1 << 15]       = C[nb][1] + bo1;
                p[8]             = C[nb][2] + bo0;
                p[(1 << 15) + 8] = C[nb][3] + bo1;
            }
        }
    }
}

// ============================================================================
extern "C" void kernel_launch(void* const* d_in, const int* in_sizes, int n_in,
                              void* d_out, int out_size) {
    const float* x    = (const float*)d_in[0];
    const float* w    = (const float*)d_in[1];
    const float* bias = (const float*)d_in[2];
    const int*   idx  = (const int*)d_in[3];
    float* out = (float*)d_out;

    (void)cudaFuncSetAttribute(k_main, cudaFuncAttributeMaxDynamicSharedMemorySize,
                               SMEM_TOTAL);

    k_transpose<<<BT_ * (NNODES_ / 32), 256>>>(x);
    k_bfrag<<<1, 256>>>(w);
    k_main<<<GRID_, 256, SMEM_TOTAL>>>(bias, idx, out);
}

// round 7
// speedup vs baseline: 1.6281x; 1.0859x over previous
#include <cuda_runtime.h>
#include <cuda_fp16.h>
#include <cstdint>
#include <cstddef>

// ============================================================================
// RandomGraphMixer3D  ==  D[M=BT*N, 32] = gather(A)[M,512] @ W'[512,32] + bias
// fp16 gather + ldmatrix + mma.sync m16n8k16, f32 accum. Warp-autonomous.
// R7: m32 per warp (tile=256 nodes) -> B-frag smem traffic halved per work;
//     idx held in registers (u16-packed), distributed to gather via shfl.
//     NBUF=3 / PF=2 per-warp cp.async ring; zero barriers in main loop.
// ============================================================================

#define BT_     16
#define NNODES_ 32768
#define NR_     16
#define NTILES_ 2048          // BT_ * NNODES_/256
#define NBUF_   3
#define PF_     2             // PF_ < NBUF_
#define GRID_   296           // 2 CTAs/SM

// SMEM layout (bytes)
#define OFF_B    0            // 32 KB B-frag table
#define OFF_BIAS 32768        // 128 B
#define OFF_A    32896        // 8 warps x 3 bufs x 2560 B
#define WARP_AB  7680         // NBUF_*2560 per warp
#define SMEM_TOTAL (32896 + 8*WARP_AB)   // 94336 -> 2 CTAs/SM

__device__ __forceinline__ uint32_t smem_u32(const void* p) {
    uint32_t a;
    asm("{ .reg .u64 t; cvta.to.shared.u64 t, %1; cvt.u32.u64 %0, t; }" : "=r"(a) : "l"(p));
    return a;
}
__device__ __forceinline__ void cp_async16(uint32_t dst, const void* src) {
    asm volatile("cp.async.cg.shared.global [%0], [%1], 16;" :: "r"(dst), "l"(src) : "memory");
}
__device__ __forceinline__ void cp_commit() {
    asm volatile("cp.async.commit_group;" ::: "memory");
}
template <int N> __device__ __forceinline__ void cp_wait() {
    asm volatile("cp.async.wait_group %0;" :: "n"(N) : "memory");
}
__device__ __forceinline__ void ldmatrix_x4(uint32_t& r0, uint32_t& r1,
                                            uint32_t& r2, uint32_t& r3, uint32_t a) {
    asm volatile("ldmatrix.sync.aligned.m8n8.x4.shared.b16 {%0,%1,%2,%3}, [%4];"
                 : "=r"(r0), "=r"(r1), "=r"(r2), "=r"(r3) : "r"(a));
}
__device__ __forceinline__ void lds128(uint32_t* v, uint32_t a) {
    asm volatile("ld.shared.v4.b32 {%0,%1,%2,%3}, [%4];"
                 : "=r"(v[0]), "=r"(v[1]), "=r"(v[2]), "=r"(v[3]) : "r"(a));
}
__device__ __forceinline__ void mma16816(float* c, const uint32_t* a,
                                         uint32_t b0, uint32_t b1) {
    asm volatile(
        "mma.sync.aligned.m16n8k16.row.col.f32.f16.f16.f32 "
        "{%0,%1,%2,%3}, {%4,%5,%6,%7}, {%8,%9}, {%0,%1,%2,%3};"
        : "+f"(c[0]), "+f"(c[1]), "+f"(c[2]), "+f"(c[3])
        : "r"(a[0]), "r"(a[1]), "r"(a[2]), "r"(a[3]), "r"(b0), "r"(b1));
}

// -------- scratch ------------------------------------------------------------
__device__ __align__(128) __half   g_xt[(size_t)BT_ * NNODES_ * 32];  // 32 MB
__device__ __align__(128) uint32_t g_Bfrag[8192];                      // 32 KB

// ============================================================================
// Kernel 1: x[b][c][n] f32 -> xt[b][n][c] f16 (8-B vectorized stores)
// ============================================================================
__global__ void k_transpose(const float* __restrict__ x) {
    __shared__ float tile[32][33];
    int b = blockIdx.x >> 10;
    int n0 = (blockIdx.x & 1023) << 5;
    int tn = threadIdx.x & 31, tc = threadIdx.x >> 5;
    const float* xb = x + ((size_t)b << 20);
#pragma unroll
    for (int p = 0; p < 4; p++) {
        int c = tc + p * 8;
        tile[c][tn] = xb[((size_t)c << 15) + n0 + tn];
    }
    __syncthreads();
    int n = threadIdx.x >> 3, q = threadIdx.x & 7;
    int c0 = q * 4;
    __half2 h01 = __halves2half2(__float2half(tile[c0][n]),
                                 __float2half(tile[c0 + 1][n]));
    __half2 h23 = __halves2half2(__float2half(tile[c0 + 2][n]),
                                 __float2half(tile[c0 + 3][n]));
    uint2 v = make_uint2(*(uint32_t*)&h01, *(uint32_t*)&h23);
    *(uint2*)((char*)(g_xt + ((size_t)b << 20)) + (size_t)(n0 + n) * 64 + q * 8) = v;
}

// ============================================================================
// Kernel 1b: per-lane B fragment table (layout validated R5/R6).
// ============================================================================
__global__ void k_bfrag(const float* __restrict__ w) {
    for (int e = threadIdx.x; e < 8192; e += blockDim.x) {
        int lane = (e >> 2) & 31, j = e & 3;
        int chunk = (e >> 7) & 1, kc = (e >> 8) & 1, r = e >> 9;
        int nb = chunk * 2 + (j >> 1), reg = j & 1;
        int n_o = nb * 8 + (lane >> 2);
        int c = kc * 16 + 2 * (lane & 3) + reg * 8;
        __half lo = __float2half(w[n_o * 512 + c * 16 + r]);
        __half hi = __float2half(w[n_o * 512 + (c + 1) * 16 + r]);
        __half2 v = __halves2half2(lo, hi);
        g_Bfrag[e] = *(uint32_t*)&v;
    }
}

// ============================================================================
// Kernel 2: persistent gather-GEMM, m32/warp (296 CTAs x 256, 2/SM)
// ============================================================================
__global__ void __launch_bounds__(256, 2)
k_main(const float* __restrict__ bias, const int* __restrict__ idxg,
       float* __restrict__ out) {
    extern __shared__ char smem[];
    uint32_t sb = smem_u32(smem);
    int tid = threadIdx.x;
    int wid = tid >> 5, lane = tid & 31;

    int nt = 0;
    for (int t = blockIdx.x; t < NTILES_; t += GRID_) nt++;

    const float* bias_s = (const float*)(smem + OFF_BIAS);
    uint32_t aw_base = sb + OFF_A + (uint32_t)wid * WARP_AB;

    // ---- idx registers: lane owns row `lane` of its warp's 32 rows --------
    // cur[q]: indices for r = 2q (low u16), 2q+1 (high u16)
    uint32_t curi[8], nxti[8];
    auto idx_fetch = [&](int ti, uint32_t* dst) {   // ti = tile index (valid)
        int nbase = (ti & 127) << 8;
        const int4* src = (const int4*)idxg
                        + ((size_t)(nbase + wid * 32 + lane) << 2);
#pragma unroll
        for (int q = 0; q < 4; q++) {
            int4 v = __ldg(src + q);
            dst[2 * q]     = ((uint32_t)v.x & 0xFFFFu) | ((uint32_t)v.y << 16);
            dst[2 * q + 1] = ((uint32_t)v.z & 0xFFFFu) | ((uint32_t)v.w << 16);
        }
    };

    // gather one r-stage of tile-iter ip into warp-private buffer buf
    auto gather = [&](int ip, int r, int buf, const uint32_t* idxp) {
        int t = blockIdx.x + ip * GRID_;
        int b = t >> 7;
        const char* xtb = (const char*)g_xt + ((size_t)b << 21);
        uint32_t abase = aw_base + (uint32_t)buf * 2560;
        int u = lane & 3;
#pragma unroll
        for (int p = 0; p < 4; p++) {
            int row = (lane >> 2) + p * 8;
            uint32_t pk = __shfl_sync(0xffffffffu, idxp[r >> 1], row);
            uint32_t g = (r & 1) ? (pk >> 16) : (pk & 0xFFFFu);
            cp_async16(abase + (uint32_t)row * 80 + (uint32_t)u * 16,
                       xtb + ((size_t)g << 6) + u * 16);
        }
    };

    // ---- prologue: B table + bias; idx(tile0); PF gathers ----
    {
        const char* src = (const char*)g_Bfrag;
#pragma unroll
        for (int k = 0; k < 8; k++)
            cp_async16(sb + OFF_B + (uint32_t)(tid + k * 256) * 16,
                       src + (tid + k * 256) * 16);
        if (tid < 8)
            cp_async16(sb + OFF_BIAS + (uint32_t)tid * 16,
                       (const char*)bias + tid * 16);
        cp_commit();
        cp_wait<0>();
        __syncthreads();     // only barrier (B-table visibility)
    }
    if (nt == 0) return;
    idx_fetch(blockIdx.x, curi);
#pragma unroll
    for (int s = 0; s < PF_; s++) { gather(0, s, s, curi); cp_commit(); }

    // consumer addressing: warp owns rows [wid*32, wid*32+32), all 32 o's
    uint32_t a_lane_off = (uint32_t)(lane & 15) * 80 + ((lane >> 4) << 4);
    uint32_t b_lane = sb + OFF_B + (uint32_t)lane * 16;

    int cons_buf = 0, pf_buf = PF_;

    for (int i = 0; i < nt; i++) {
        int t = blockIdx.x + i * GRID_;
        int b = t >> 7;
        int nb_node = (t & 127) << 8;

        float C[2][4][4];
#pragma unroll
        for (int mb = 0; mb < 2; mb++)
#pragma unroll
            for (int nb = 0; nb < 4; nb++)
#pragma unroll
                for (int j = 0; j < 4; j++) C[mb][nb][j] = 0.0f;

#pragma unroll
        for (int r = 0; r < NR_; r++) {
            if (r == 0) {      // prefetch next tile's idx (hidden latency)
                int tsafe = (i + 1 < nt) ? (blockIdx.x + (i + 1) * GRID_)
                                         : blockIdx.x;
                idx_fetch(tsafe, nxti);
            }
            if (r == 14) {     // switch to next tile's idx before boundary
#pragma unroll
                for (int q = 0; q < 8; q++) curi[q] = nxti[q];
            }
            // issue gather for global stage +PF
            {
                int ip  = i + ((r + PF_) >> 4);
                int pfr = (r + PF_) & 15;
                if (ip < nt) gather(ip, pfr, pf_buf, curi);
                cp_commit();                       // keep group count aligned
                if (++pf_buf == NBUF_) pf_buf = 0;
            }
            cp_wait<PF_>();

            uint32_t abuf = aw_base + (uint32_t)cons_buf * 2560 + a_lane_off;
            uint32_t bst = b_lane + (uint32_t)r * 2048;
#pragma unroll
            for (int kc = 0; kc < 2; kc++) {
                uint32_t bf0[4], bf1[4];
                lds128(bf0, bst + (uint32_t)kc * 1024);         // nb0,nb1
                lds128(bf1, bst + (uint32_t)kc * 1024 + 512);   // nb2,nb3
#pragma unroll
                for (int mb = 0; mb < 2; mb++) {
                    uint32_t a[4];
                    ldmatrix_x4(a[0], a[1], a[2], a[3],
                                abuf + (uint32_t)mb * 1280 + kc * 32);
                    mma16816(C[mb][0], a, bf0[0], bf0[1]);
                    mma16816(C[mb][1], a, bf0[2], bf0[3]);
                    mma16816(C[mb][2], a, bf1[0], bf1[1]);
                    mma16816(C[mb][3], a, bf1[2], bf1[3]);
                }
            }
            if (++cons_buf == NBUF_) cons_buf = 0;
        }

        // ---- epilogue: bias + store ----
        {
            int oo = 2 * (lane & 3);
            float* ob0 = out + ((size_t)b << 20) + nb_node + wid * 32 + (lane >> 2);
#pragma unroll
            for (int mb = 0; mb < 2; mb++) {
                float* ob = ob0 + mb * 16;
#pragma unroll
                for (int nb = 0; nb < 4; nb++) {
                    int o = nb * 8 + oo;
                    float bo0 = bias_s[o], bo1 = bias_s[o + 1];
                    float* p = ob + ((size_t)o << 15);
                    p[0]             = C[mb][nb][0] + bo0;
                    p[1 << 15]       = C[mb][nb][1] + bo1;
                    p[8]             = C[mb][nb][2] + bo0;
                    p[(1 << 15) + 8] = C[mb][nb][3] + bo1;
                }
            }
        }
    }
}

// ============================================================================
extern "C" void kernel_launch(void* const* d_in, const int* in_sizes, int n_in,
                              void* d_out, int out_size) {
    const float* x    = (const float*)d_in[0];
    const float* w    = (const float*)d_in[1];
    const float* bias = (const float*)d_in[2];
    const int*   idx  = (const int*)d_in[3];
    float* out = (float*)d_out;

    (void)cudaFuncSetAttribute(k_main, cudaFuncAttributeMaxDynamicSharedMemorySize,
                               SMEM_TOTAL);

    k_transpose<<<BT_ * (NNODES_ / 32), 256>>>(x);
    k_bfrag<<<1, 256>>>(w);
    k_main<<<GRID_, 256, SMEM_TOTAL>>>(bias, idx, out);
}